// round 1
// baseline (speedup 1.0000x reference)
#include <cuda_runtime.h>
#include <math.h>

// ---------------- problem constants ----------------
#define BB    2
#define LL    4096
#define DD    512
#define HH    8
#define DHD   64
#define MM    266
#define NROWS (BB*LL)        // 8192
#define CHUNK 64
#define NCH   (LL/CHUNK)     // 64
#define BHT   (BB*HH)        // 16

#define INV_S4      0.21022410381342863f   // 512^-0.25
#define INV_SQRT512 0.04419417382415922f   // 512^-0.5

// ---------------- scratch (device globals; cudaMalloc is banned) ----------------
__device__ float g_Q[NROWS*DD];
__device__ float g_K[NROWS*DD];
__device__ float g_V[NROWS*DD];
__device__ float g_hq[NROWS*HH];
__device__ float g_hk[NROWS*HH];
__device__ float g_qp[(size_t)BHT*LL*MM];              // [b][h][l][m]
__device__ float g_kp[(size_t)BHT*LL*MM];
__device__ float g_S [(size_t)BHT*NCH*MM*DHD];         // [bh][c][m][d]
__device__ float g_z [(size_t)BHT*NCH*MM];             // [bh][c][m]
__device__ float g_ctx[NROWS*DD];

// ---------------- GEMM: C[n,o] = sum_k A[n,k]*W[o,k] + b[o]  (8192x512x512) ----------------
__global__ void __launch_bounds__(256) gemm_nt_bias(const float* __restrict__ A,
                                                    const float* __restrict__ W,
                                                    const float* __restrict__ bias,
                                                    float* __restrict__ C) {
    __shared__ float As[16][65];
    __shared__ float Ws[16][65];
    const int tx = threadIdx.x & 15, ty = threadIdx.x >> 4;
    const int row0 = blockIdx.y * 64, col0 = blockIdx.x * 64;
    float acc[4][4];
    #pragma unroll
    for (int i = 0; i < 4; i++)
        #pragma unroll
        for (int j = 0; j < 4; j++) acc[i][j] = 0.f;

    for (int k0 = 0; k0 < DD; k0 += 16) {
        #pragma unroll
        for (int i = 0; i < 4; i++) {
            int idx = threadIdx.x + i * 256;   // 0..1023
            int r = idx >> 4, kk = idx & 15;
            As[kk][r] = A[(size_t)(row0 + r) * DD + k0 + kk];
            Ws[kk][r] = W[(size_t)(col0 + r) * DD + k0 + kk];
        }
        __syncthreads();
        #pragma unroll
        for (int kk = 0; kk < 16; kk++) {
            float a[4], w[4];
            #pragma unroll
            for (int i = 0; i < 4; i++) a[i] = As[kk][ty * 4 + i];
            #pragma unroll
            for (int j = 0; j < 4; j++) w[j] = Ws[kk][tx * 4 + j];
            #pragma unroll
            for (int i = 0; i < 4; i++)
                #pragma unroll
                for (int j = 0; j < 4; j++) acc[i][j] += a[i] * w[j];
        }
        __syncthreads();
    }
    #pragma unroll
    for (int i = 0; i < 4; i++) {
        int r = row0 + ty * 4 + i;
        #pragma unroll
        for (int j = 0; j < 4; j++) {
            int cidx = col0 + tx * 4 + j;
            C[(size_t)r * DD + cidx] = acc[i][j] + bias[cidx];
        }
    }
}

// ---------------- per-(row,head) -0.5*||x/scale||^2 ----------------
__global__ void hq_kernel(const float* __restrict__ X, float* __restrict__ hout) {
    int row = blockIdx.x;
    int w = threadIdx.x >> 5, lane = threadIdx.x & 31;
    const float* xr = X + (size_t)row * DD + w * DHD;
    float2 v = *(const float2*)&xr[lane * 2];
    float s = v.x * v.x + v.y * v.y;
    #pragma unroll
    for (int off = 16; off; off >>= 1) s += __shfl_xor_sync(0xffffffffu, s, off);
    if (lane == 0) hout[(size_t)row * HH + w] = -0.5f * INV_SQRT512 * s;
}

// ---------------- feature map: out[b][h][l][m] = exp(hq + (x/scale)·RF[m]) ----------------
__global__ void __launch_bounds__(256) feat_gemm(const float* __restrict__ X,
                                                 const float* __restrict__ RF,
                                                 const float* __restrict__ hv,
                                                 float* __restrict__ outp) {
    __shared__ float as[64][65];   // [d][row]
    __shared__ float rs[64][65];   // [d][m]
    const int tx = threadIdx.x & 15, ty = threadIdx.x >> 4;
    const int h  = blockIdx.z;
    const int r0 = blockIdx.y * 64;       // global row = b*LL + l
    const int m0 = blockIdx.x * 64;

    for (int idx = threadIdx.x; idx < 4096; idx += 256) {
        int row = idx >> 6, d = idx & 63;
        as[d][row] = X[(size_t)(r0 + row) * DD + h * DHD + d] * INV_S4;
        int m = m0 + row;
        rs[d][row] = (m < MM) ? RF[(size_t)m * DHD + d] : 0.f;
    }
    __syncthreads();

    float acc[4][4];
    #pragma unroll
    for (int i = 0; i < 4; i++)
        #pragma unroll
        for (int j = 0; j < 4; j++) acc[i][j] = 0.f;

    #pragma unroll 8
    for (int kk = 0; kk < 64; kk++) {
        float a[4], bm[4];
        #pragma unroll
        for (int i = 0; i < 4; i++) a[i] = as[kk][ty * 4 + i];
        #pragma unroll
        for (int j = 0; j < 4; j++) bm[j] = rs[kk][tx * 4 + j];
        #pragma unroll
        for (int i = 0; i < 4; i++)
            #pragma unroll
            for (int j = 0; j < 4; j++) acc[i][j] += a[i] * bm[j];
    }

    #pragma unroll
    for (int i = 0; i < 4; i++) {
        int r = r0 + ty * 4 + i;
        float hval = hv[(size_t)r * HH + h];
        int b = r >> 12, l = r & 4095;
        size_t base = (((size_t)(b * HH + h)) * LL + l) * MM;
        #pragma unroll
        for (int j = 0; j < 4; j++) {
            int m = m0 + tx * 4 + j;
            if (m < MM) outp[base + m] = expf(acc[i][j] + hval);
        }
    }
}

// ---------------- phase A: per-chunk S_c = K'^T V, z_c = sum k' ----------------
__global__ void __launch_bounds__(256) phaseA_kernel() {
    __shared__ float sk[8][272];
    __shared__ float sv[8][68];
    const int tx = threadIdx.x & 15;   // d group (float4)
    const int ty = threadIdx.x >> 4;   // m base
    const int c = blockIdx.x, h = blockIdx.y, b = blockIdx.z;
    const int bh = b * HH + h;
    const int l0 = c * CHUNK;
    const float* kb = g_kp + ((size_t)bh * LL + l0) * MM;
    const float* vb = g_V + ((size_t)(b * LL + l0)) * DD + h * DHD;

    float acc[17][4];
    float zacc[17];
    #pragma unroll
    for (int i = 0; i < 17; i++) {
        zacc[i] = 0.f;
        #pragma unroll
        for (int j = 0; j < 4; j++) acc[i][j] = 0.f;
    }

    for (int t0 = 0; t0 < CHUNK; t0 += 8) {
        for (int idx = threadIdx.x; idx < 8 * MM; idx += 256) {
            int t = idx / MM, mm = idx % MM;
            sk[t][mm] = kb[(size_t)(t0 + t) * MM + mm];
        }
        for (int idx = threadIdx.x; idx < 8 * 64; idx += 256) {
            int t = idx >> 6, d = idx & 63;
            sv[t][d] = vb[(size_t)(t0 + t) * DD + d];
        }
        __syncthreads();
        #pragma unroll
        for (int t = 0; t < 8; t++) {
            float4 v4 = *(float4*)&sv[t][tx * 4];
            #pragma unroll
            for (int i = 0; i < 17; i++) {
                float a = sk[t][ty + 16 * i];   // padded; invalid m never stored
                acc[i][0] += a * v4.x; acc[i][1] += a * v4.y;
                acc[i][2] += a * v4.z; acc[i][3] += a * v4.w;
                zacc[i] += a;
            }
        }
        __syncthreads();
    }
    float* Sb = g_S + ((size_t)bh * NCH + c) * (MM * DHD);
    float* zb = g_z + ((size_t)bh * NCH + c) * MM;
    #pragma unroll
    for (int i = 0; i < 17; i++) {
        int m = ty + 16 * i;
        if (m < MM) {
            float4 o = make_float4(acc[i][0], acc[i][1], acc[i][2], acc[i][3]);
            *(float4*)&Sb[(size_t)m * DHD + tx * 4] = o;
            if (tx == 0) zb[m] = zacc[i];
        }
    }
}

// ---------------- phase B: exclusive prefix over chunks (per element) ----------------
__global__ void scan_kernel(float* data, int per) {
    int gid = blockIdx.x * blockDim.x + threadIdx.x;
    if (gid >= BHT * per) return;
    int bh = gid / per, e = gid % per;
    size_t base = (size_t)bh * NCH * per + e;
    float run = 0.f;
    #pragma unroll 4
    for (int c = 0; c < NCH; c++) {
        size_t idx = base + (size_t)c * per;
        float cur = data[idx];
        data[idx] = run;
        run += cur;
    }
}

// ---------------- phase C: per-chunk outputs ----------------
__global__ void __launch_bounds__(256) phaseC_kernel() {
    __shared__ float A_sh[64 * 65];
    __shared__ float work[64 * 68];   // reused: (qs+ks) -> Vs -> (qs2+Ss+zs)
    const int tx = threadIdx.x & 15, ty = threadIdx.x >> 4;
    const int c = blockIdx.x, h = blockIdx.y, b = blockIdx.z;
    const int bh = b * HH + h;
    const int l0 = c * CHUNK;
    const float* qbase = g_qp + ((size_t)bh * LL + l0) * MM;
    const float* kbase = g_kp + ((size_t)bh * LL + l0) * MM;

    // ---- gemm1: A = Q' K'^T over M=266 ----
    float acc[4][4];
    #pragma unroll
    for (int i = 0; i < 4; i++)
        #pragma unroll
        for (int j = 0; j < 4; j++) acc[i][j] = 0.f;

    float* qs = work;
    float* ks = work + 2080;          // 32*65
    for (int m0 = 0; m0 < MM; m0 += 32) {
        for (int idx = threadIdx.x; idx < 64 * 32; idx += 256) {
            int kk = idx & 31, t = idx >> 5;
            int m = m0 + kk;
            float qv = 0.f, kv = 0.f;
            if (m < MM) {
                qv = qbase[(size_t)t * MM + m];
                kv = kbase[(size_t)t * MM + m];
            }
            qs[kk * 65 + t] = qv;
            ks[kk * 65 + t] = kv;
        }
        __syncthreads();
        #pragma unroll 4
        for (int kk = 0; kk < 32; kk++) {
            float a[4], bb2[4];
            #pragma unroll
            for (int i = 0; i < 4; i++) a[i] = qs[kk * 65 + ty * 4 + i];
            #pragma unroll
            for (int j = 0; j < 4; j++) bb2[j] = ks[kk * 65 + tx * 4 + j];
            #pragma unroll
            for (int i = 0; i < 4; i++)
                #pragma unroll
                for (int j = 0; j < 4; j++) acc[i][j] += a[i] * bb2[j];
        }
        __syncthreads();
    }
    // causal mask -> A_sh
    #pragma unroll
    for (int i = 0; i < 4; i++) {
        int t = ty * 4 + i;
        #pragma unroll
        for (int j = 0; j < 4; j++) {
            int s = tx * 4 + j;
            A_sh[t * 65 + s] = (s <= t) ? acc[i][j] : 0.f;
        }
    }
    // load V chunk into work
    for (int idx = threadIdx.x; idx < 64 * 64; idx += 256) {
        int d = idx & 63, t = idx >> 6;
        work[t * 68 + d] = g_V[((size_t)(b * LL + l0 + t)) * DD + h * DHD + d];
    }
    __syncthreads();

    // ---- gemm2: num = A*V, den = rowsum(A) ----
    float num[4][4];
    float den[4];
    #pragma unroll
    for (int i = 0; i < 4; i++) {
        den[i] = 0.f;
        #pragma unroll
        for (int j = 0; j < 4; j++) num[i][j] = 0.f;
    }
    #pragma unroll 4
    for (int j = 0; j < 64; j++) {
        float a[4];
        #pragma unroll
        for (int i = 0; i < 4; i++) a[i] = A_sh[(ty * 4 + i) * 65 + j];
        float4 v = *(float4*)&work[j * 68 + tx * 4];
        #pragma unroll
        for (int i = 0; i < 4; i++) {
            num[i][0] += a[i] * v.x; num[i][1] += a[i] * v.y;
            num[i][2] += a[i] * v.z; num[i][3] += a[i] * v.w;
            den[i] += a[i];
        }
    }
    __syncthreads();

    // ---- inter-chunk: num += Q'*S_prefix, den += Q'*z_prefix ----
    const float* Sbase = g_S + ((size_t)bh * NCH + c) * (MM * DHD);
    const float* zbase = g_z + ((size_t)bh * NCH + c) * MM;
    float* qs2 = work;                // 32*65
    float* Ss  = work + 2080;         // 32*68
    float* zs  = work + 4256;         // 32
    for (int m0 = 0; m0 < MM; m0 += 32) {
        for (int idx = threadIdx.x; idx < 64 * 32; idx += 256) {
            int kk = idx & 31, t = idx >> 5;
            int m = m0 + kk;
            qs2[kk * 65 + t] = (m < MM) ? qbase[(size_t)t * MM + m] : 0.f;
        }
        for (int idx = threadIdx.x; idx < 32 * 64; idx += 256) {
            int d = idx & 63, kk = idx >> 6;
            int m = m0 + kk;
            Ss[kk * 68 + d] = (m < MM) ? Sbase[(size_t)m * DHD + d] : 0.f;
        }
        if (threadIdx.x < 32) {
            int m = m0 + threadIdx.x;
            zs[threadIdx.x] = (m < MM) ? zbase[m] : 0.f;
        }
        __syncthreads();
        #pragma unroll 4
        for (int kk = 0; kk < 32; kk++) {
            float a[4];
            #pragma unroll
            for (int i = 0; i < 4; i++) a[i] = qs2[kk * 65 + ty * 4 + i];
            float4 s4 = *(float4*)&Ss[kk * 68 + tx * 4];
            float zz = zs[kk];
            #pragma unroll
            for (int i = 0; i < 4; i++) {
                num[i][0] += a[i] * s4.x; num[i][1] += a[i] * s4.y;
                num[i][2] += a[i] * s4.z; num[i][3] += a[i] * s4.w;
                den[i] += a[i] * zz;
            }
        }
        __syncthreads();
    }

    // ---- epilogue: ctx = num/den ----
    #pragma unroll
    for (int i = 0; i < 4; i++) {
        int t = ty * 4 + i;
        float invd = 1.0f / den[i];
        size_t base = ((size_t)(b * LL + l0 + t)) * DD + h * DHD + tx * 4;
        #pragma unroll
        for (int j = 0; j < 4; j++) g_ctx[base + j] = num[i][j] * invd;
    }
}

// ---------------- launch ----------------
extern "C" void kernel_launch(void* const* d_in, const int* in_sizes, int n_in,
                              void* d_out, int out_size) {
    const float* query = (const float*)d_in[0];
    const float* key   = (const float*)d_in[1];
    const float* value = (const float*)d_in[2];
    const float* Wq    = (const float*)d_in[3];
    const float* bq    = (const float*)d_in[4];
    const float* Wk    = (const float*)d_in[5];
    const float* bk    = (const float*)d_in[6];
    const float* Wv    = (const float*)d_in[7];
    const float* bv    = (const float*)d_in[8];
    const float* Wout  = (const float*)d_in[9];
    const float* bout  = (const float*)d_in[10];
    const float* RF    = (const float*)d_in[11];

    float *Qp, *Kp, *Vp, *hqp, *hkp, *qpp, *kpp, *Sp, *zp, *ctxp;
    cudaGetSymbolAddress((void**)&Qp,  g_Q);
    cudaGetSymbolAddress((void**)&Kp,  g_K);
    cudaGetSymbolAddress((void**)&Vp,  g_V);
    cudaGetSymbolAddress((void**)&hqp, g_hq);
    cudaGetSymbolAddress((void**)&hkp, g_hk);
    cudaGetSymbolAddress((void**)&qpp, g_qp);
    cudaGetSymbolAddress((void**)&kpp, g_kp);
    cudaGetSymbolAddress((void**)&Sp,  g_S);
    cudaGetSymbolAddress((void**)&zp,  g_z);
    cudaGetSymbolAddress((void**)&ctxp, g_ctx);

    dim3 gg(DD / 64, NROWS / 64);   // (8, 128)
    gemm_nt_bias<<<gg, 256>>>(query, Wq, bq, Qp);
    gemm_nt_bias<<<gg, 256>>>(key,   Wk, bk, Kp);
    gemm_nt_bias<<<gg, 256>>>(value, Wv, bv, Vp);

    hq_kernel<<<NROWS, 256>>>(Qp, hqp);
    hq_kernel<<<NROWS, 256>>>(Kp, hkp);

    dim3 fg((MM + 63) / 64, NROWS / 64, HH);   // (5, 128, 8)
    feat_gemm<<<fg, 256>>>(Qp, RF, hqp, qpp);
    feat_gemm<<<fg, 256>>>(Kp, RF, hkp, kpp);

    dim3 pg(NCH, HH, BB);   // (64, 8, 2)
    phaseA_kernel<<<pg, 256>>>();

    int perS = MM * DHD;
    scan_kernel<<<(BHT * perS + 255) / 256, 256>>>(Sp, perS);
    scan_kernel<<<(BHT * MM + 255) / 256, 256>>>(zp, MM);

    phaseC_kernel<<<pg, 256>>>();

    gemm_nt_bias<<<gg, 256>>>(ctxp, Wout, bout, (float*)d_out);
}

// round 2
// speedup vs baseline: 1.2825x; 1.2825x over previous
#include <cuda_runtime.h>
#include <math.h>

// ---------------- problem constants ----------------
#define BB    2
#define LL    4096
#define DD    512
#define HH    8
#define DHD   64
#define MM    266
#define NROWS (BB*LL)        // 8192
#define CHUNK 64
#define NCH   (LL/CHUNK)     // 64
#define BHT   (BB*HH)        // 16

#define INV_S4      0.21022410381342863f   // 512^-0.25
#define INV_SQRT512 0.04419417382415922f   // 512^-0.5

// ---------------- scratch (device globals; cudaMalloc is banned) ----------------
__device__ float g_Q[NROWS*DD];
__device__ float g_K[NROWS*DD];
__device__ float g_V[NROWS*DD];
__device__ float g_hq[NROWS*HH];
__device__ float g_hk[NROWS*HH];
__device__ float g_qp[(size_t)BHT*LL*MM];              // [b][h][l][m]
__device__ float g_kp[(size_t)BHT*LL*MM];
__device__ float g_S [(size_t)BHT*NCH*MM*DHD];         // [bh][c][m][d]
__device__ float g_z [(size_t)BHT*NCH*MM];             // [bh][c][m]
__device__ float g_ctx[NROWS*DD];

// ---------------- SGEMM 128x128, BK=8, 8x8 microtile, double-buffered ----------------
// C[n,o] = sum_k A[n,k]*W[o,k] + bias[o];  A:[8192,512] W:[512,512] both K-contiguous.
// If batched (gridDim.z==3), blockIdx.z selects (A,W,bias,C) set.
__global__ void __launch_bounds__(256, 2)
sgemm128(const float* __restrict__ A0, const float* __restrict__ W0,
         const float* __restrict__ b0, float* __restrict__ C0,
         const float* __restrict__ A1, const float* __restrict__ W1,
         const float* __restrict__ b1, float* __restrict__ C1,
         const float* __restrict__ A2, const float* __restrict__ W2,
         const float* __restrict__ b2, float* __restrict__ C2) {
    __shared__ float As[2][8][132];
    __shared__ float Ws[2][8][132];

    const float* A; const float* W; const float* bias; float* C;
    if (blockIdx.z == 0)      { A = A0; W = W0; bias = b0; C = C0; }
    else if (blockIdx.z == 1) { A = A1; W = W1; bias = b1; C = C1; }
    else                      { A = A2; W = W2; bias = b2; C = C2; }

    const int t = threadIdx.x;
    const int row0 = blockIdx.y * 128, col0 = blockIdx.x * 128;
    const int lr = t >> 1;              // 0..127 load row
    const int lk = (t & 1) * 4;         // 0 or 4

    const int ty = t >> 4, tx = t & 15; // 16x16 thread grid, 8x8 microtile

    float acc[8][8];
    #pragma unroll
    for (int i = 0; i < 8; i++)
        #pragma unroll
        for (int j = 0; j < 8; j++) acc[i][j] = 0.f;

    // load first k-tile
    float4 aS = *(const float4*)&A[(size_t)(row0 + lr) * DD + lk];
    float4 wS = *(const float4*)&W[(size_t)(col0 + lr) * DD + lk];
    #pragma unroll
    for (int i = 0; i < 4; i++) {
        As[0][lk + i][lr] = ((const float*)&aS)[i];
        Ws[0][lk + i][lr] = ((const float*)&wS)[i];
    }
    __syncthreads();

    int buf = 0;
    for (int kt = 0; kt < DD / 8; kt++) {
        float4 aN, wN;
        if (kt < DD / 8 - 1) {
            int k0 = (kt + 1) * 8;
            aN = *(const float4*)&A[(size_t)(row0 + lr) * DD + k0 + lk];
            wN = *(const float4*)&W[(size_t)(col0 + lr) * DD + k0 + lk];
        }
        #pragma unroll
        for (int k = 0; k < 8; k++) {
            float4 a0 = *(float4*)&As[buf][k][ty * 8];
            float4 a1 = *(float4*)&As[buf][k][ty * 8 + 4];
            float4 w0 = *(float4*)&Ws[buf][k][tx * 8];
            float4 w1 = *(float4*)&Ws[buf][k][tx * 8 + 4];
            float a[8] = {a0.x,a0.y,a0.z,a0.w,a1.x,a1.y,a1.z,a1.w};
            float w[8] = {w0.x,w0.y,w0.z,w0.w,w1.x,w1.y,w1.z,w1.w};
            #pragma unroll
            for (int i = 0; i < 8; i++)
                #pragma unroll
                for (int j = 0; j < 8; j++) acc[i][j] += a[i] * w[j];
        }
        if (kt < DD / 8 - 1) {
            #pragma unroll
            for (int i = 0; i < 4; i++) {
                As[buf ^ 1][lk + i][lr] = ((const float*)&aN)[i];
                Ws[buf ^ 1][lk + i][lr] = ((const float*)&wN)[i];
            }
            __syncthreads();
            buf ^= 1;
        }
    }

    #pragma unroll
    for (int i = 0; i < 8; i++) {
        size_t r = row0 + ty * 8 + i;
        #pragma unroll
        for (int j = 0; j < 8; j += 4) {
            int cidx = col0 + tx * 8 + j;
            float4 o = make_float4(acc[i][j] + bias[cidx],
                                   acc[i][j+1] + bias[cidx+1],
                                   acc[i][j+2] + bias[cidx+2],
                                   acc[i][j+3] + bias[cidx+3]);
            *(float4*)&C[r * DD + cidx] = o;
        }
    }
}

// ---------------- per-(row,head) -0.5*||x/scale||^2 ----------------
__global__ void hq_kernel(const float* __restrict__ X, float* __restrict__ hout) {
    int row = blockIdx.x;
    int w = threadIdx.x >> 5, lane = threadIdx.x & 31;
    const float* xr = X + (size_t)row * DD + w * DHD;
    float2 v = *(const float2*)&xr[lane * 2];
    float s = v.x * v.x + v.y * v.y;
    #pragma unroll
    for (int off = 16; off; off >>= 1) s += __shfl_xor_sync(0xffffffffu, s, off);
    if (lane == 0) hout[(size_t)row * HH + w] = -0.5f * INV_SQRT512 * s;
}

// ---------------- feature map: out[b][h][l][m] = exp(hq + (x/scale)·RF[m]) ----------------
// 128 rows x 64 m per block, K=64 in 4 chunks of 16, 8x4 microtile.
__global__ void __launch_bounds__(256) feat_gemm(const float* __restrict__ X,
                                                 const float* __restrict__ RF,
                                                 const float* __restrict__ hv,
                                                 float* __restrict__ outp) {
    __shared__ float Xs[16][132];   // [k][row]
    __shared__ float Rs[16][68];    // [k][m]
    const int t = threadIdx.x;
    const int h  = blockIdx.z;
    const int r0 = blockIdx.y * 128;
    const int m0 = blockIdx.x * 64;
    const int ty = t >> 4, tx = t & 15;   // rows ty*8, cols tx*4

    float acc[8][4];
    #pragma unroll
    for (int i = 0; i < 8; i++)
        #pragma unroll
        for (int j = 0; j < 4; j++) acc[i][j] = 0.f;

    const int xr = t & 127;           // row for X load
    const int xk = (t >> 7) * 8;      // 0 or 8
    const int rm = t & 63;            // m for RF load
    const int rk = (t >> 6) * 4;      // 0,4,8,12

    for (int kc = 0; kc < DHD; kc += 16) {
        // load X[128 rows][16 k] (scaled), transposed
        float4 x0 = *(const float4*)&X[(size_t)(r0 + xr) * DD + h * DHD + kc + xk];
        float4 x1 = *(const float4*)&X[(size_t)(r0 + xr) * DD + h * DHD + kc + xk + 4];
        #pragma unroll
        for (int i = 0; i < 4; i++) {
            Xs[xk + i][xr]     = ((const float*)&x0)[i] * INV_S4;
            Xs[xk + 4 + i][xr] = ((const float*)&x1)[i] * INV_S4;
        }
        // load RF[64 m][16 k], transposed, guarded
        int mg = m0 + rm;
        float4 rv = make_float4(0.f, 0.f, 0.f, 0.f);
        if (mg < MM) rv = *(const float4*)&RF[(size_t)mg * DHD + kc + rk];
        #pragma unroll
        for (int i = 0; i < 4; i++) Rs[rk + i][rm] = ((const float*)&rv)[i];
        __syncthreads();

        #pragma unroll
        for (int k = 0; k < 16; k++) {
            float4 a0 = *(float4*)&Xs[k][ty * 8];
            float4 a1 = *(float4*)&Xs[k][ty * 8 + 4];
            float4 bb = *(float4*)&Rs[k][tx * 4];
            float a[8] = {a0.x,a0.y,a0.z,a0.w,a1.x,a1.y,a1.z,a1.w};
            float w[4] = {bb.x,bb.y,bb.z,bb.w};
            #pragma unroll
            for (int i = 0; i < 8; i++)
                #pragma unroll
                for (int j = 0; j < 4; j++) acc[i][j] += a[i] * w[j];
        }
        __syncthreads();
    }

    #pragma unroll
    for (int i = 0; i < 8; i++) {
        int r = r0 + ty * 8 + i;
        float hval = hv[(size_t)r * HH + h];
        int b = r >> 12, l = r & 4095;
        size_t base = (((size_t)(b * HH + h)) * LL + l) * MM;
        #pragma unroll
        for (int j = 0; j < 4; j++) {
            int m = m0 + tx * 4 + j;
            if (m < MM) outp[base + m] = expf(acc[i][j] + hval);
        }
    }
}

// ---------------- phase A: per-chunk S_c = K'^T V, z_c = sum k' ----------------
__global__ void __launch_bounds__(256) phaseA_kernel() {
    __shared__ float sk[8][272];
    __shared__ float sv[8][68];
    const int tx = threadIdx.x & 15;   // d group (float4)
    const int ty = threadIdx.x >> 4;   // m base
    const int c = blockIdx.x, h = blockIdx.y, b = blockIdx.z;
    const int bh = b * HH + h;
    const int l0 = c * CHUNK;
    const float* kb = g_kp + ((size_t)bh * LL + l0) * MM;
    const float* vb = g_V + ((size_t)(b * LL + l0)) * DD + h * DHD;

    float acc[17][4];
    float zacc[17];
    #pragma unroll
    for (int i = 0; i < 17; i++) {
        zacc[i] = 0.f;
        #pragma unroll
        for (int j = 0; j < 4; j++) acc[i][j] = 0.f;
    }

    for (int t0 = 0; t0 < CHUNK; t0 += 8) {
        for (int idx = threadIdx.x; idx < 8 * MM; idx += 256) {
            int t = idx / MM, mm = idx % MM;
            sk[t][mm] = kb[(size_t)(t0 + t) * MM + mm];
        }
        for (int idx = threadIdx.x; idx < 8 * 64; idx += 256) {
            int t = idx >> 6, d = idx & 63;
            sv[t][d] = vb[(size_t)(t0 + t) * DD + d];
        }
        __syncthreads();
        #pragma unroll
        for (int t = 0; t < 8; t++) {
            float4 v4 = *(float4*)&sv[t][tx * 4];
            #pragma unroll
            for (int i = 0; i < 17; i++) {
                float a = sk[t][ty + 16 * i];
                acc[i][0] += a * v4.x; acc[i][1] += a * v4.y;
                acc[i][2] += a * v4.z; acc[i][3] += a * v4.w;
                zacc[i] += a;
            }
        }
        __syncthreads();
    }
    float* Sb = g_S + ((size_t)bh * NCH + c) * (MM * DHD);
    float* zb = g_z + ((size_t)bh * NCH + c) * MM;
    #pragma unroll
    for (int i = 0; i < 17; i++) {
        int m = ty + 16 * i;
        if (m < MM) {
            float4 o = make_float4(acc[i][0], acc[i][1], acc[i][2], acc[i][3]);
            *(float4*)&Sb[(size_t)m * DHD + tx * 4] = o;
            if (tx == 0) zb[m] = zacc[i];
        }
    }
}

// ---------------- phase B: exclusive prefix over chunks (per element) ----------------
__global__ void scan_kernel(float* data, int per) {
    int gid = blockIdx.x * blockDim.x + threadIdx.x;
    if (gid >= BHT * per) return;
    int bh = gid / per, e = gid % per;
    size_t base = (size_t)bh * NCH * per + e;
    float run = 0.f;
    #pragma unroll 4
    for (int c = 0; c < NCH; c++) {
        size_t idx = base + (size_t)c * per;
        float cur = data[idx];
        data[idx] = run;
        run += cur;
    }
}

// ---------------- phase C: per-chunk outputs ----------------
__global__ void __launch_bounds__(256) phaseC_kernel() {
    __shared__ float A_sh[64 * 65];
    __shared__ float work[64 * 68];   // reused: (qs+ks) -> Vs -> (qs2+Ss+zs)
    const int tx = threadIdx.x & 15, ty = threadIdx.x >> 4;
    const int c = blockIdx.x, h = blockIdx.y, b = blockIdx.z;
    const int bh = b * HH + h;
    const int l0 = c * CHUNK;
    const float* qbase = g_qp + ((size_t)bh * LL + l0) * MM;
    const float* kbase = g_kp + ((size_t)bh * LL + l0) * MM;

    // ---- gemm1: A = Q' K'^T over M=266 ----
    float acc[4][4];
    #pragma unroll
    for (int i = 0; i < 4; i++)
        #pragma unroll
        for (int j = 0; j < 4; j++) acc[i][j] = 0.f;

    float* qs = work;
    float* ks = work + 2080;          // 32*65
    for (int m0 = 0; m0 < MM; m0 += 32) {
        for (int idx = threadIdx.x; idx < 64 * 32; idx += 256) {
            int kk = idx & 31, t = idx >> 5;
            int m = m0 + kk;
            float qv = 0.f, kv = 0.f;
            if (m < MM) {
                qv = qbase[(size_t)t * MM + m];
                kv = kbase[(size_t)t * MM + m];
            }
            qs[kk * 65 + t] = qv;
            ks[kk * 65 + t] = kv;
        }
        __syncthreads();
        #pragma unroll 4
        for (int kk = 0; kk < 32; kk++) {
            float a[4], bb2[4];
            #pragma unroll
            for (int i = 0; i < 4; i++) a[i] = qs[kk * 65 + ty * 4 + i];
            #pragma unroll
            for (int j = 0; j < 4; j++) bb2[j] = ks[kk * 65 + tx * 4 + j];
            #pragma unroll
            for (int i = 0; i < 4; i++)
                #pragma unroll
                for (int j = 0; j < 4; j++) acc[i][j] += a[i] * bb2[j];
        }
        __syncthreads();
    }
    // causal mask -> A_sh
    #pragma unroll
    for (int i = 0; i < 4; i++) {
        int t = ty * 4 + i;
        #pragma unroll
        for (int j = 0; j < 4; j++) {
            int s = tx * 4 + j;
            A_sh[t * 65 + s] = (s <= t) ? acc[i][j] : 0.f;
        }
    }
    // load V chunk into work
    for (int idx = threadIdx.x; idx < 64 * 64; idx += 256) {
        int d = idx & 63, t = idx >> 6;
        work[t * 68 + d] = g_V[((size_t)(b * LL + l0 + t)) * DD + h * DHD + d];
    }
    __syncthreads();

    // ---- gemm2: num = A*V, den = rowsum(A) ----
    float num[4][4];
    float den[4];
    #pragma unroll
    for (int i = 0; i < 4; i++) {
        den[i] = 0.f;
        #pragma unroll
        for (int j = 0; j < 4; j++) num[i][j] = 0.f;
    }
    #pragma unroll 4
    for (int j = 0; j < 64; j++) {
        float a[4];
        #pragma unroll
        for (int i = 0; i < 4; i++) a[i] = A_sh[(ty * 4 + i) * 65 + j];
        float4 v = *(float4*)&work[j * 68 + tx * 4];
        #pragma unroll
        for (int i = 0; i < 4; i++) {
            num[i][0] += a[i] * v.x; num[i][1] += a[i] * v.y;
            num[i][2] += a[i] * v.z; num[i][3] += a[i] * v.w;
            den[i] += a[i];
        }
    }
    __syncthreads();

    // ---- inter-chunk: num += Q'*S_prefix, den += Q'*z_prefix ----
    const float* Sbase = g_S + ((size_t)bh * NCH + c) * (MM * DHD);
    const float* zbase = g_z + ((size_t)bh * NCH + c) * MM;
    float* qs2 = work;                // 32*65
    float* Ss  = work + 2080;         // 32*68
    float* zs  = work + 4256;         // 32
    for (int m0 = 0; m0 < MM; m0 += 32) {
        for (int idx = threadIdx.x; idx < 64 * 32; idx += 256) {
            int kk = idx & 31, t = idx >> 5;
            int m = m0 + kk;
            qs2[kk * 65 + t] = (m < MM) ? qbase[(size_t)t * MM + m] : 0.f;
        }
        for (int idx = threadIdx.x; idx < 32 * 64; idx += 256) {
            int d = idx & 63, kk = idx >> 6;
            int m = m0 + kk;
            Ss[kk * 68 + d] = (m < MM) ? Sbase[(size_t)m * DHD + d] : 0.f;
        }
        if (threadIdx.x < 32) {
            int m = m0 + threadIdx.x;
            zs[threadIdx.x] = (m < MM) ? zbase[m] : 0.f;
        }
        __syncthreads();
        #pragma unroll 4
        for (int kk = 0; kk < 32; kk++) {
            float a[4];
            #pragma unroll
            for (int i = 0; i < 4; i++) a[i] = qs2[kk * 65 + ty * 4 + i];
            float4 s4 = *(float4*)&Ss[kk * 68 + tx * 4];
            float zz = zs[kk];
            #pragma unroll
            for (int i = 0; i < 4; i++) {
                num[i][0] += a[i] * s4.x; num[i][1] += a[i] * s4.y;
                num[i][2] += a[i] * s4.z; num[i][3] += a[i] * s4.w;
                den[i] += a[i] * zz;
            }
        }
        __syncthreads();
    }

    // ---- epilogue: ctx = num/den ----
    #pragma unroll
    for (int i = 0; i < 4; i++) {
        int t = ty * 4 + i;
        float invd = 1.0f / den[i];
        size_t base = ((size_t)(b * LL + l0 + t)) * DD + h * DHD + tx * 4;
        #pragma unroll
        for (int j = 0; j < 4; j++) g_ctx[base + j] = num[i][j] * invd;
    }
}

// ---------------- launch ----------------
extern "C" void kernel_launch(void* const* d_in, const int* in_sizes, int n_in,
                              void* d_out, int out_size) {
    const float* query = (const float*)d_in[0];
    const float* key   = (const float*)d_in[1];
    const float* value = (const float*)d_in[2];
    const float* Wq    = (const float*)d_in[3];
    const float* bq    = (const float*)d_in[4];
    const float* Wk    = (const float*)d_in[5];
    const float* bk    = (const float*)d_in[6];
    const float* Wv    = (const float*)d_in[7];
    const float* bv    = (const float*)d_in[8];
    const float* Wout  = (const float*)d_in[9];
    const float* bout  = (const float*)d_in[10];
    const float* RF    = (const float*)d_in[11];

    float *Qp, *Kp, *Vp, *hqp, *hkp, *qpp, *kpp, *Sp, *zp, *ctxp;
    cudaGetSymbolAddress((void**)&Qp,  g_Q);
    cudaGetSymbolAddress((void**)&Kp,  g_K);
    cudaGetSymbolAddress((void**)&Vp,  g_V);
    cudaGetSymbolAddress((void**)&hqp, g_hq);
    cudaGetSymbolAddress((void**)&hkp, g_hk);
    cudaGetSymbolAddress((void**)&qpp, g_qp);
    cudaGetSymbolAddress((void**)&kpp, g_kp);
    cudaGetSymbolAddress((void**)&Sp,  g_S);
    cudaGetSymbolAddress((void**)&zp,  g_z);
    cudaGetSymbolAddress((void**)&ctxp, g_ctx);

    // batched Q/K/V projections: grid.z selects the GEMM
    dim3 gp(DD / 128, NROWS / 128, 3);   // (4, 64, 3)
    sgemm128<<<gp, 256>>>(query, Wq, bq, Qp,
                          key,   Wk, bk, Kp,
                          value, Wv, bv, Vp);

    hq_kernel<<<NROWS, 256>>>(Qp, hqp);
    hq_kernel<<<NROWS, 256>>>(Kp, hkp);

    dim3 fg((MM + 63) / 64, NROWS / 128, HH);   // (5, 64, 8)
    feat_gemm<<<fg, 256>>>(Qp, RF, hqp, qpp);
    feat_gemm<<<fg, 256>>>(Kp, RF, hkp, kpp);

    dim3 pg(NCH, HH, BB);   // (64, 8, 2)
    phaseA_kernel<<<pg, 256>>>();

    int perS = MM * DHD;
    scan_kernel<<<(BHT * perS + 255) / 256, 256>>>(Sp, perS);
    scan_kernel<<<(BHT * MM + 255) / 256, 256>>>(zp, MM);

    phaseC_kernel<<<pg, 256>>>();

    // output projection
    dim3 go(DD / 128, NROWS / 128, 1);
    sgemm128<<<go, 256>>>(ctxp, Wout, bout, (float*)d_out,
                          ctxp, Wout, bout, (float*)d_out,
                          ctxp, Wout, bout, (float*)d_out);
}